// round 15
// baseline (speedup 1.0000x reference)
#include <cuda_runtime.h>
#include <cuda_bf16.h>
#include <cstdint>

#define BB 16
#define SS 2048
#define DD 64
#define TQ 64
#define NJ 64
#define NT 128
#define NTILES (SS / NJ)

// dynamic smem: Q hi/lo (16KB) + K hi/lo (16KB) + V hi/lo (16KB) + inv
#define OQH 0
#define OQL 8192
#define OKH 16384
#define OKL 24576
#define OVH 32768
#define OVL 40960
#define OINV 49152
#define SMEM_DYN (49152 + 256 + 1024)

#define SWZ(o) ((o) ^ (((o) >> 3) & 0x70u))
#define QSCALE 0.1803368801111249f   // 0.125 * log2(e)

// mask bitmap scratch: 16 batches x 2048 rows x 64 words (2048 bits) = 8 MB
__device__ uint32_t g_mb[BB * SS * (SS / 32)];

static __device__ __forceinline__ uint32_t packbf(float lo, float hi) {
    uint32_t r;
    asm("cvt.rn.bf16x2.f32 %0, %1, %2;" : "=r"(r) : "f"(hi), "f"(lo));
    return r;
}
static __device__ __forceinline__ float ubf(uint32_t u) { return __uint_as_float(u); }

static __device__ __forceinline__ void ldsm4(uint32_t* r, uint32_t a) {
    asm volatile("ldmatrix.sync.aligned.m8n8.x4.shared.b16 {%0,%1,%2,%3}, [%4];"
        : "=r"(r[0]), "=r"(r[1]), "=r"(r[2]), "=r"(r[3]) : "r"(a));
}
static __device__ __forceinline__ void ldsm4t(uint32_t* r, uint32_t a) {
    asm volatile("ldmatrix.sync.aligned.m8n8.x4.trans.shared.b16 {%0,%1,%2,%3}, [%4];"
        : "=r"(r[0]), "=r"(r[1]), "=r"(r[2]), "=r"(r[3]) : "r"(a));
}
static __device__ __forceinline__ void mma16816(float* c, const uint32_t* a,
                                                uint32_t b0, uint32_t b1) {
    asm volatile("mma.sync.aligned.m16n8k16.row.col.f32.bf16.bf16.f32 "
        "{%0,%1,%2,%3}, {%4,%5,%6,%7}, {%8,%9}, {%0,%1,%2,%3};"
        : "+f"(c[0]), "+f"(c[1]), "+f"(c[2]), "+f"(c[3])
        : "r"(a[0]), "r"(a[1]), "r"(a[2]), "r"(a[3]), "r"(b0), "r"(b1));
}
static __device__ __forceinline__ uint32_t s2u(const void* p) {
    uint32_t a;
    asm("{ .reg .u64 t; cvta.to.shared.u64 t, %1; cvt.u32.u64 %0, t; }" : "=r"(a) : "l"(p));
    return a;
}
static __device__ __forceinline__ uint32_t b2b(uint32_t wv, int sh) {
    uint32_t r = 0;
    r |= ((wv & 0x000000FFu) ? 1u : 0u) << sh;
    r |= ((wv & 0x0000FF00u) ? 1u : 0u) << (sh + 1);
    r |= ((wv & 0x00FF0000u) ? 1u : 0u) << (sh + 2);
    r |= ((wv & 0xFF000000u) ? 1u : 0u) << (sh + 3);
    return r;
}

// stage a [64 x 64] fp32 tile as bf16 hi/lo into SW128 smem (128 threads)
static __device__ __forceinline__ void stage_bf(const float* __restrict__ g,
                                                char* sh, char* sl, float sc, int tid)
{
#pragma unroll
    for (int it = 0; it < 4; it++) {
        int i = it * NT + tid;
        int row = i >> 3, c8 = (i & 7) << 3;
        float4 a = *(const float4*)(g + row * 64 + c8);
        float4 b = *(const float4*)(g + row * 64 + c8 + 4);
        float y[8] = {a.x*sc, a.y*sc, a.z*sc, a.w*sc, b.x*sc, b.y*sc, b.z*sc, b.w*sc};
        uint32_t h[4], l[4];
#pragma unroll
        for (int p = 0; p < 4; p++) {
            h[p] = packbf(y[2*p], y[2*p+1]);
            float f0 = ubf(h[p] << 16), f1 = ubf(h[p] & 0xFFFF0000u);
            l[p] = packbf(y[2*p] - f0, y[2*p+1] - f1);
        }
        uint32_t off = SWZ((uint32_t)(row * 128 + c8 * 2));
        *(uint4*)(sh + off) = make_uint4(h[0], h[1], h[2], h[3]);
        *(uint4*)(sl + off) = make_uint4(l[0], l[1], l[2], l[3]);
    }
}

__global__ __launch_bounds__(NT, 4) void sdpa_mma_kernel(
    const float* __restrict__ q, const float* __restrict__ k,
    const float* __restrict__ v, const void* __restrict__ maskp,
    float* __restrict__ out, float* __restrict__ attn)
{
    const int b   = blockIdx.y;
    const int q0  = blockIdx.x * TQ;
    const int tid = threadIdx.x;
    const int w   = tid >> 5;
    const int lid = tid & 31;
    const int g   = lid >> 2;
    const int t2  = lid & 3;
    const int bq  = b * SS + q0;

    extern __shared__ char dsm_raw[];
    char* dsm = (char*)(((uintptr_t)dsm_raw + 1023) & ~(uintptr_t)1023);
    float* sInv = (float*)(dsm + OINV);
    const uint32_t uQH = s2u(dsm + OQH), uQL = s2u(dsm + OQL);
    const uint32_t uKH = s2u(dsm + OKH), uKL = s2u(dsm + OKL);
    const uint32_t uVH = s2u(dsm + OVH), uVL = s2u(dsm + OVL);

    const float* qb = q + ((size_t)bq) * DD;
    const float* kb = k + (size_t)b * SS * DD;
    const float* vb = v + (size_t)b * SS * DD;
    const unsigned char* m8b  = (const unsigned char*)maskp + (size_t)b * SS * SS;
    const uint32_t*      m32b = (const uint32_t*)maskp + (size_t)b * SS * SS;

    // ---- fused mask-dtype detect over this CTA's own slice ----
    int pF = 0, pB = 0;
    {
        uint4 u = __ldcs((const uint4*)(m32b + (size_t)q0 * SS) + tid);
        uint32_t ws[4] = {u.x, u.y, u.z, u.w};
#pragma unroll
        for (int i = 0; i < 4; i++) {
            if (ws[i] == 0x3F800000u) pF = 1;
            else if (ws[i] > 1u)      pB = 1;
        }
    }

    // Q staged once, pre-scaled by 0.125*log2(e) (epilogue uses exp2f)
    stage_bf(qb, dsm + OQH, dsm + OQL, QSCALE, tid);

    const int anyF = __syncthreads_or(pF);
    const int anyB = __syncthreads_or(pB);
    const int mk = anyF ? 2 : (anyB ? 0 : 1);   // 0=uint8, 1=int32, 2=float32

    // ldmatrix lane address patterns
    const int krow = (lid & 7) + ((lid >> 4) & 1) * 8;
    const int kbyt = ((lid >> 3) & 1) * 16;
    const int qrow = (lid & 7) + ((lid >> 3) & 1) * 8;
    const int qbyt = ((lid >> 4) & 1) * 16;

    // mask lane roles
    const int rsel = t2 >> 1;
    const int half = t2 & 1;
    const int qb4  = g * 4;
    const size_t mwbase = (size_t)(bq + w * 16 + g + rsel * 8) * (SS / 32);

    float OD[8][4];
#pragma unroll
    for (int i = 0; i < 8; i++)
#pragma unroll
        for (int jx = 0; jx < 4; jx++) OD[i][jx] = 0.f;

    float rs0 = 0.f, rs1 = 0.f;

    // =================== PHASE A: rowsums + PV (no attn writes) ===================
    for (int t = 0; t < NTILES; t++) {
        const int j0 = t * NJ;

        if (t > 0) __syncthreads();
        stage_bf(kb + (size_t)j0 * DD, dsm + OKH, dsm + OKL, 1.0f, tid);
        stage_bf(vb + (size_t)j0 * DD, dsm + OVH, dsm + OVL, 1.0f, tid);
        __syncthreads();

        // hoisted mask loads (consumed after GEMM1)
        const size_t mrow = (size_t)(q0 + w * 16 + g + rsel * 8) * SS + j0 + half * 32;
        uint4 hma, hmb;
        uint32_t myb = 0;
        if (mk == 0) {
            const uint4* p0 = (const uint4*)(m8b + mrow);
            hma = __ldcs(p0); hmb = __ldcs(p0 + 1);
        } else {
            const uint4* p0 = (const uint4*)(m32b + mrow);
#pragma unroll
            for (int ii = 0; ii < 8; ii++) {
                uint4 a = __ldcs(p0 + ii);
                myb |= (a.x?1u:0u)<<(ii*4)   | (a.y?1u:0u)<<(ii*4+1)
                     | (a.z?1u:0u)<<(ii*4+2) | (a.w?1u:0u)<<(ii*4+3);
            }
        }

        // ---- GEMM1: C[8][4] = Q(16q) x K^T(64j), 3-term bf16 split ----
        float C[8][4];
#pragma unroll
        for (int fn = 0; fn < 8; fn++)
#pragma unroll
            for (int jx = 0; jx < 4; jx++) C[fn][jx] = 0.f;

#pragma unroll
        for (int ks = 0; ks < 4; ks++) {
            uint32_t qh[4], ql[4];
            uint32_t qoff = (uint32_t)(w * 2048 +
                (((qrow * 128) | (ks * 32) | qbyt) ^ ((qrow & 7) << 4)));
            ldsm4(qh, uQH + qoff);
            ldsm4(ql, uQL + qoff);
#pragma unroll
            for (int jg = 0; jg < 4; jg++) {
                uint32_t kh[4], kl[4];
                uint32_t koff = (uint32_t)(jg * 2048 +
                    (((krow * 128) | (ks * 32) | kbyt) ^ ((krow & 7) << 4)));
                ldsm4(kh, uKH + koff);
                ldsm4(kl, uKL + koff);
                mma16816(C[2*jg],   qh, kh[0], kh[1]);
                mma16816(C[2*jg+1], qh, kh[2], kh[3]);
                mma16816(C[2*jg],   qh, kl[0], kl[1]);
                mma16816(C[2*jg+1], qh, kl[2], kl[3]);
                mma16816(C[2*jg],   ql, kh[0], kh[1]);
                mma16816(C[2*jg+1], ql, kh[2], kh[3]);
            }
        }

        // pack mask bits, persist to bitmap, distribute
        if (mk == 0) {
            myb = b2b(hma.x,0)|b2b(hma.y,4)|b2b(hma.z,8)|b2b(hma.w,12)
                | b2b(hmb.x,16)|b2b(hmb.y,20)|b2b(hmb.z,24)|b2b(hmb.w,28);
        }
        g_mb[mwbase + t * 2 + half] = myb;
        uint32_t mw0[2], mw1[2];
#pragma unroll
        for (int i = 0; i < 2; i++) {
            mw0[i] = __shfl_sync(0xffffffffu, myb, qb4 + i);
            mw1[i] = __shfl_sync(0xffffffffu, myb, qb4 + 2 + i);
        }

        // ---- per-slab epilogue + GEMM2 (no attn store) ----
#pragma unroll
        for (int jj = 0; jj < 4; jj++) {
            uint32_t phi[4], plo[4];
#pragma unroll
            for (int fo = 0; fo < 2; fo++) {
                const int fn = 2 * jj + fo;
                const int wsel = jj >> 1;
                const int sh = (jj & 1) * 16 + fo * 8 + t2 * 2;
                uint32_t w0 = mw0[wsel], w1 = mw1[wsel];
                float* Cf = C[fn];
                float p0 = ((w0 >> sh) & 1u)       ? 0.f : exp2f(Cf[0]);
                float p1 = ((w0 >> (sh + 1)) & 1u) ? 0.f : exp2f(Cf[1]);
                float p2 = ((w1 >> sh) & 1u)       ? 0.f : exp2f(Cf[2]);
                float p3 = ((w1 >> (sh + 1)) & 1u) ? 0.f : exp2f(Cf[3]);
                rs0 += p0 + p1;
                rs1 += p2 + p3;

                uint32_t h01 = packbf(p0, p1), h23 = packbf(p2, p3);
                float f0 = ubf(h01 << 16), f1 = ubf(h01 & 0xFFFF0000u);
                float f2 = ubf(h23 << 16), f3 = ubf(h23 & 0xFFFF0000u);
                int o = fo * 2;
                phi[o] = h01; phi[o + 1] = h23;
                plo[o] = packbf(p0 - f0, p1 - f1);
                plo[o + 1] = packbf(p2 - f2, p3 - f3);
            }
#pragma unroll
            for (int dg = 0; dg < 4; dg++) {
                uint32_t vh[4], vl[4];
                uint32_t voff = (uint32_t)(jj * 2048 +
                    (((qrow * 128) | (dg * 32) | qbyt) ^ ((qrow & 7) << 4)));
                ldsm4t(vh, uVH + voff);
                ldsm4t(vl, uVL + voff);
                mma16816(OD[2*dg],   phi, vh[0], vh[1]);
                mma16816(OD[2*dg+1], phi, vh[2], vh[3]);
                mma16816(OD[2*dg],   phi, vl[0], vl[1]);
                mma16816(OD[2*dg+1], phi, vl[2], vl[3]);
                mma16816(OD[2*dg],   plo, vh[0], vh[1]);
                mma16816(OD[2*dg+1], plo, vh[2], vh[3]);
            }
        }
    }

    // ---- row sums + output ----
    rs0 += __shfl_xor_sync(0xffffffffu, rs0, 1);
    rs0 += __shfl_xor_sync(0xffffffffu, rs0, 2);
    rs1 += __shfl_xor_sync(0xffffffffu, rs1, 1);
    rs1 += __shfl_xor_sync(0xffffffffu, rs1, 2);
    const float inv0 = 1.0f / rs0, inv1 = 1.0f / rs1;

    float* o0 = out + (size_t)(bq + w * 16 + g) * DD;
    float* o1 = o0 + (size_t)8 * DD;
#pragma unroll
    for (int dn = 0; dn < 8; dn++) {
        *(float2*)(o0 + dn * 8 + t2 * 2) = make_float2(OD[dn][0] * inv0, OD[dn][1] * inv0);
        *(float2*)(o1 + dn * 8 + t2 * 2) = make_float2(OD[dn][2] * inv1, OD[dn][3] * inv1);
    }

    // =================== PHASE B: recompute scores, write normalized attn ===================
    for (int t = 0; t < NTILES; t++) {
        const int j0 = t * NJ;

        __syncthreads();
        stage_bf(kb + (size_t)j0 * DD, dsm + OKH, dsm + OKL, 1.0f, tid);
        __syncthreads();

        // hoisted bitmap load (this lane's own phase-A write)
        uint32_t myb = g_mb[mwbase + t * 2 + half];

        float C[8][4];
#pragma unroll
        for (int fn = 0; fn < 8; fn++)
#pragma unroll
            for (int jx = 0; jx < 4; jx++) C[fn][jx] = 0.f;

#pragma unroll
        for (int ks = 0; ks < 4; ks++) {
            uint32_t qh[4], ql[4];
            uint32_t qoff = (uint32_t)(w * 2048 +
                (((qrow * 128) | (ks * 32) | qbyt) ^ ((qrow & 7) << 4)));
            ldsm4(qh, uQH + qoff);
            ldsm4(ql, uQL + qoff);
#pragma unroll
            for (int jg = 0; jg < 4; jg++) {
                uint32_t kh[4], kl[4];
                uint32_t koff = (uint32_t)(jg * 2048 +
                    (((krow * 128) | (ks * 32) | kbyt) ^ ((krow & 7) << 4)));
                ldsm4(kh, uKH + koff);
                ldsm4(kl, uKL + koff);
                mma16816(C[2*jg],   qh, kh[0], kh[1]);
                mma16816(C[2*jg+1], qh, kh[2], kh[3]);
                mma16816(C[2*jg],   qh, kl[0], kl[1]);
                mma16816(C[2*jg+1], qh, kl[2], kl[3]);
                mma16816(C[2*jg],   ql, kh[0], kh[1]);
                mma16816(C[2*jg+1], ql, kh[2], kh[3]);
            }
        }

        uint32_t mw0[2], mw1[2];
#pragma unroll
        for (int i = 0; i < 2; i++) {
            mw0[i] = __shfl_sync(0xffffffffu, myb, qb4 + i);
            mw1[i] = __shfl_sync(0xffffffffu, myb, qb4 + 2 + i);
        }

        float* ar0 = attn + ((size_t)(bq + w * 16 + g)) * SS + j0;
        float* ar1 = ar0 + (size_t)8 * SS;

#pragma unroll
        for (int jj = 0; jj < 4; jj++) {
#pragma unroll
            for (int fo = 0; fo < 2; fo++) {
                const int fn = 2 * jj + fo;
                const int wsel = jj >> 1;
                const int sh = (jj & 1) * 16 + fo * 8 + t2 * 2;
                uint32_t w0 = mw0[wsel], w1 = mw1[wsel];
                float* Cf = C[fn];
                // identical floats to (raw p) * inv from the old normalize pass
                float p0 = ((w0 >> sh) & 1u)       ? 0.f : exp2f(Cf[0]) * inv0;
                float p1 = ((w0 >> (sh + 1)) & 1u) ? 0.f : exp2f(Cf[1]) * inv0;
                float p2 = ((w1 >> sh) & 1u)       ? 0.f : exp2f(Cf[2]) * inv1;
                float p3 = ((w1 >> (sh + 1)) & 1u) ? 0.f : exp2f(Cf[3]) * inv1;
                __stcs((float2*)(ar0 + fn * 8 + t2 * 2), make_float2(p0, p1));
                __stcs((float2*)(ar1 + fn * 8 + t2 * 2), make_float2(p2, p3));
            }
        }
    }
}

extern "C" void kernel_launch(void* const* d_in, const int* in_sizes, int n_in,
                              void* d_out, int out_size)
{
    const float* q = (const float*)d_in[0];
    const float* k = (const float*)d_in[1];
    const float* v = (const float*)d_in[2];
    const void*  mask = d_in[3];

    float* out  = (float*)d_out;
    float* attn = out + (size_t)BB * SS * DD;   // tuple order: (output, attn)

    cudaFuncSetAttribute(sdpa_mma_kernel,
                         cudaFuncAttributeMaxDynamicSharedMemorySize, SMEM_DYN);

    dim3 grid(SS / TQ, BB);
    sdpa_mma_kernel<<<grid, NT, SMEM_DYN>>>(q, k, v, mask, out, attn);
}